// round 1
// baseline (speedup 1.0000x reference)
#include <cuda_runtime.h>
#include <cstdint>

#define NROWS   131072
#define DIMS    32
#define NC      512
#define NC2     256          // center pairs
#define NBLKGRID 148
#define NTHREADS 512
#define ROWBLKS  4096        // NROWS / 32

// smem layout (bytes):
//   [0      , 65536) : pair-interleaved centers: float2 sc2[c2*32 + d] = {C[2c2][d], C[2c2+1][d]}
//   [65536  , 69632) : coef float4 scoef[c2] = {a0, a1, b0, b1}   a=-0.5*L/s^2, b=a*csq
//   [69632  , 71680) : float2 sg[c2] = {g0, g1}                   g= L/s^2
//   [71680  , 77824) : float2 sw[c2*3+k] = {W[k][2c2], W[k][2c2+1]}
#define SMEM_BYTES 77824

#define FMA2(acc, a, b) \
    asm("fma.rn.f32x2 %0, %1, %2, %0;" : "+l"(acc) : "l"(a), "l"(b))

__device__ __forceinline__ unsigned long long dup2(float v) {
    unsigned long long r; unsigned u = __float_as_uint(v);
    asm("mov.b64 %0, {%1, %1};" : "=l"(r) : "r"(u));
    return r;
}

__global__ void __launch_bounds__(NTHREADS, 1)
rbfn_kernel(const float* __restrict__ X,    // [N, D]
            const float* __restrict__ Cn,   // [C, D]
            const float* __restrict__ Sg,   // [1, C]
            const float* __restrict__ Wp,   // [DO, C]
            const float* __restrict__ Bp,   // [DO]
            float* __restrict__ O)          // [N, DO]
{
    extern __shared__ unsigned char smem_raw[];
    float2* sc2   = (float2*)(smem_raw);
    float4* scoef = (float4*)(smem_raw + 65536);
    float2* sg    = (float2*)(smem_raw + 65536 + 4096);
    float2* sw    = (float2*)(smem_raw + 65536 + 4096 + 2048);

    const int tid = threadIdx.x;

    // ---- stage centers pair-interleaved into smem ----
    for (int i = tid; i < NC2 * DIMS; i += NTHREADS) {
        int c2 = i >> 5, d = i & 31;
        sc2[c2 * 32 + d] = make_float2(Cn[(2 * c2) * DIMS + d],
                                       Cn[(2 * c2 + 1) * DIMS + d]);
    }
    // ---- per-center-pair folded coefficients ----
    if (tid < NC2) {
        const int c2 = tid;
        float cs0 = 0.f, cs1 = 0.f;
        const float* ca = Cn + (2 * c2) * DIMS;
        const float* cb = Cn + (2 * c2 + 1) * DIMS;
        #pragma unroll 8
        for (int d = 0; d < DIMS; ++d) {
            cs0 = fmaf(ca[d], ca[d], cs0);
            cs1 = fmaf(cb[d], cb[d], cs1);
        }
        const float L = 1.4426950408889634f;   // log2(e)
        float s0 = Sg[2 * c2];     s0 = 1.0f / (s0 * s0);
        float s1 = Sg[2 * c2 + 1]; s1 = 1.0f / (s1 * s1);
        float a0 = -0.5f * L * s0, a1 = -0.5f * L * s1;
        scoef[c2] = make_float4(a0, a1, a0 * cs0, a1 * cs1);
        sg[c2]    = make_float2(L * s0, L * s1);
        sw[c2 * 3 + 0] = make_float2(Wp[0 * NC + 2 * c2], Wp[0 * NC + 2 * c2 + 1]);
        sw[c2 * 3 + 1] = make_float2(Wp[1 * NC + 2 * c2], Wp[1 * NC + 2 * c2 + 1]);
        sw[c2 * 3 + 2] = make_float2(Wp[2 * NC + 2 * c2], Wp[2 * NC + 2 * c2 + 1]);
    }
    __syncthreads();

    const ulonglong2*         scu = (const ulonglong2*)scoef;
    const unsigned long long* sgu = (const unsigned long long*)sg;
    const unsigned long long* swu = (const unsigned long long*)sw;

    const int wid = tid >> 5, lane = tid & 31;
    const float bo0 = Bp[0], bo1 = Bp[1], bo2 = Bp[2];

    for (int j = 0; j < 2; ++j) {
        const int rb = (int)blockIdx.x + NBLKGRID * (wid + 16 * j);
        if (rb >= ROWBLKS) break;
        const int row = (rb << 5) + lane;

        // load x row, dup-pack into f32x2 lanes, accumulate ||x||^2
        const float4* xr = (const float4*)(X + (size_t)row * DIMS);
        unsigned long long xd[DIMS];
        float xsq = 0.f;
        #pragma unroll
        for (int q = 0; q < 8; ++q) {
            float4 v = xr[q];
            xsq = fmaf(v.x, v.x, xsq); xsq = fmaf(v.y, v.y, xsq);
            xsq = fmaf(v.z, v.z, xsq); xsq = fmaf(v.w, v.w, xsq);
            xd[4 * q + 0] = dup2(v.x); xd[4 * q + 1] = dup2(v.y);
            xd[4 * q + 2] = dup2(v.z); xd[4 * q + 3] = dup2(v.w);
        }
        const unsigned long long xsqd = dup2(xsq);

        unsigned long long op0 = 0ull, op1 = 0ull, op2 = 0ull;  // paired O accumulators

        for (int c2 = 0; c2 < NC2; c2 += 4) {
            unsigned long long acc[4] = {0ull, 0ull, 0ull, 0ull};
            const ulonglong2* p = (const ulonglong2*)(sc2 + c2 * 32);
            #pragma unroll
            for (int dd = 0; dd < 16; ++dd) {
                #pragma unroll
                for (int cp = 0; cp < 4; ++cp) {
                    ulonglong2 u = p[cp * 16 + dd];     // dims 2dd,2dd+1 of pair c2+cp
                    FMA2(acc[cp], xd[2 * dd],     u.x);
                    FMA2(acc[cp], xd[2 * dd + 1], u.y);
                }
            }
            #pragma unroll
            for (int cp = 0; cp < 4; ++cp) {
                ulonglong2 ab = scu[c2 + cp];
                unsigned long long g = sgu[c2 + cp];
                unsigned long long t;
                // t_half = a*xsq + b + g*cross   (= -0.5*log2e*dist2/sigma^2)
                asm("fma.rn.f32x2 %0, %1, %2, %3;" : "=l"(t)
                    : "l"(ab.x), "l"(xsqd), "l"(ab.y));
                FMA2(t, g, acc[cp]);
                unsigned t0i, t1i;
                asm("mov.b64 {%0, %1}, %2;" : "=r"(t0i), "=r"(t1i) : "l"(t));
                float r0, r1;
                asm("ex2.approx.ftz.f32 %0, %1;" : "=f"(r0) : "f"(__uint_as_float(t0i)));
                asm("ex2.approx.ftz.f32 %0, %1;" : "=f"(r1) : "f"(__uint_as_float(t1i)));
                unsigned long long rp, h;
                asm("mov.b64 %0, {%1, %2};" : "=l"(rp)
                    : "r"(__float_as_uint(r0)), "r"(__float_as_uint(r1)));
                // h = (2^(t/2))^2 : subnormal-correct via non-ftz mul
                asm("mul.rn.f32x2 %0, %1, %2;" : "=l"(h) : "l"(rp), "l"(rp));
                FMA2(op0, h, swu[(c2 + cp) * 3 + 0]);
                FMA2(op1, h, swu[(c2 + cp) * 3 + 1]);
                FMA2(op2, h, swu[(c2 + cp) * 3 + 2]);
            }
        }

        float* Or = O + (size_t)row * 3;
        unsigned lo, hi;
        asm("mov.b64 {%0, %1}, %2;" : "=r"(lo), "=r"(hi) : "l"(op0));
        Or[0] = __uint_as_float(lo) + __uint_as_float(hi) + bo0;
        asm("mov.b64 {%0, %1}, %2;" : "=r"(lo), "=r"(hi) : "l"(op1));
        Or[1] = __uint_as_float(lo) + __uint_as_float(hi) + bo1;
        asm("mov.b64 {%0, %1}, %2;" : "=r"(lo), "=r"(hi) : "l"(op2));
        Or[2] = __uint_as_float(lo) + __uint_as_float(hi) + bo2;
    }
}

extern "C" void kernel_launch(void* const* d_in, const int* in_sizes, int n_in,
                              void* d_out, int out_size)
{
    // map inputs by unique element counts (robust to ordering)
    const float* X = nullptr; const float* Cn = nullptr; const float* Sg = nullptr;
    const float* Wp = nullptr; const float* Bp = nullptr;
    for (int i = 0; i < n_in; ++i) {
        switch (in_sizes[i]) {
            case NROWS * DIMS: X  = (const float*)d_in[i]; break;  // 4194304
            case NC * DIMS:    Cn = (const float*)d_in[i]; break;  // 16384
            case NC:           Sg = (const float*)d_in[i]; break;  // 512
            case 3 * NC:       Wp = (const float*)d_in[i]; break;  // 1536
            case 3:            Bp = (const float*)d_in[i]; break;  // 3
            default: break;
        }
    }
    if (!X || !Cn || !Sg || !Wp || !Bp) {
        // positional fallback: batches, centers, sigmas, W, b
        X  = (const float*)d_in[0]; Cn = (const float*)d_in[1];
        Sg = (const float*)d_in[2]; Wp = (const float*)d_in[3];
        Bp = (const float*)d_in[4];
    }

    cudaFuncSetAttribute(rbfn_kernel,
                         cudaFuncAttributeMaxDynamicSharedMemorySize, SMEM_BYTES);
    rbfn_kernel<<<NBLKGRID, NTHREADS, SMEM_BYTES>>>(X, Cn, Sg, Wp, Bp, (float*)d_out);
}

// round 2
// speedup vs baseline: 1.3516x; 1.3516x over previous
#include <cuda_runtime.h>
#include <cstdint>

#define NROWS   131072
#define DIMS    32
#define NC      512
#define NC2     256
#define NBLK    148
#define NTH     512
#define ROWBLKS 4096
#define RBSPLIT 2368      /* NBLK * 16 warps */
#define PAIRMAX 1728      /* rb0 < PAIRMAX  ->  rb1 = rb0 + RBSPLIT < 4096 */

typedef unsigned long long u64;
typedef unsigned int       u32;

// smem layout (bytes):
//   [0      , 65536) : centers row-major float[512][32]
//   [65536  , 69632) : coef float4 scoef[c2] = {a0, a1, b0, b1}
//   [69632  , 71680) : float2 sg[c2] = {g0, g1}
//   [71680  , 77824) : float2 sw[c2*3+k]
#define SMEM_COEF 65536
#define SMEM_G    (65536 + 4096)
#define SMEM_W    (65536 + 4096 + 2048)
#define SMEM_BYTES (65536 + 4096 + 2048 + 6144)

#define FMA2(acc, a, b) \
    asm("fma.rn.f32x2 %0, %1, %2, %0;" : "+l"(acc) : "l"(a), "l"(b))

__device__ __forceinline__ u64 dup2(float v) {
    u64 r; u32 u = __float_as_uint(v);
    asm("mov.b64 %0, {%1, %1};" : "=l"(r) : "r"(u));
    return r;
}
__device__ __forceinline__ u64 pack2(u32 a, u32 b) {
    u64 r; asm("mov.b64 %0, {%1, %2};" : "=l"(r) : "r"(a), "r"(b));
    return r;
}
__device__ __forceinline__ void unpack2(u64 v, u32& a, u32& b) {
    asm("mov.b64 {%0, %1}, %2;" : "=r"(a), "=r"(b) : "l"(v));
}

// Process R rows (R = 1 or 2) against all 512 centers.
template<int R>
__device__ __forceinline__ void process_rows(
    const float* __restrict__ X, float* __restrict__ O,
    int row0, int row1, const unsigned char* smem_raw,
    float bo0, float bo1, float bo2)
{
    const ulonglong2* sc    = (const ulonglong2*)(smem_raw);             // 8 per center
    const ulonglong2* scoef = (const ulonglong2*)(smem_raw + SMEM_COEF); // {a0,a1},{b0,b1}
    const u64*        sg    = (const u64*)(smem_raw + SMEM_G);
    const u64*        sw    = (const u64*)(smem_raw + SMEM_W);

    int rows[2] = { row0, row1 };

    // x rows as packed dim-pairs + dup'd ||x||^2
    u64 xp[R][16];
    u64 xsqd[R];
    #pragma unroll
    for (int r = 0; r < R; ++r) {
        const ulonglong2* xr = (const ulonglong2*)(X + (size_t)rows[r] * DIMS);
        u64 sq = 0ull;
        #pragma unroll
        for (int q = 0; q < 8; ++q) {
            ulonglong2 v = xr[q];
            xp[r][2 * q]     = v.x;
            xp[r][2 * q + 1] = v.y;
            FMA2(sq, v.x, v.x);
            FMA2(sq, v.y, v.y);
        }
        u32 lo, hi; unpack2(sq, lo, hi);
        xsqd[r] = dup2(__uint_as_float(lo) + __uint_as_float(hi));
    }

    u64 op[3][R];
    #pragma unroll
    for (int k = 0; k < 3; ++k)
        #pragma unroll
        for (int r = 0; r < R; ++r) op[k][r] = 0ull;

    for (int c4 = 0; c4 < NC; c4 += 4) {
        u64 acc[4][R];
        #pragma unroll
        for (int cp = 0; cp < 4; ++cp)
            #pragma unroll
            for (int r = 0; r < R; ++r) acc[cp][r] = 0ull;

        const ulonglong2* p = sc + (size_t)c4 * 8;
        #pragma unroll
        for (int cp = 0; cp < 4; ++cp) {
            #pragma unroll
            for (int d8 = 0; d8 < 8; ++d8) {
                ulonglong2 u = p[cp * 8 + d8];         // 4 dims of center c4+cp
                #pragma unroll
                for (int r = 0; r < R; ++r) {
                    FMA2(acc[cp][r], xp[r][2 * d8],     u.x);
                    FMA2(acc[cp][r], xp[r][2 * d8 + 1], u.y);
                }
            }
        }

        // epilogue: two center-pairs (c4,c4+1) and (c4+2,c4+3), packed over centers
        #pragma unroll
        for (int pp = 0; pp < 2; ++pp) {
            const int c2 = (c4 >> 1) + pp;
            ulonglong2 ab = scoef[c2];
            u64 g  = sg[c2];
            u64 w0 = sw[c2 * 3 + 0], w1 = sw[c2 * 3 + 1], w2 = sw[c2 * 3 + 2];
            #pragma unroll
            for (int r = 0; r < R; ++r) {
                u32 aLo, aHi, bLo, bHi;
                unpack2(acc[2 * pp][r],     aLo, aHi);
                unpack2(acc[2 * pp + 1][r], bLo, bHi);
                u64 pe = pack2(aLo, bLo);   // even-dim partials of both centers
                u64 po = pack2(aHi, bHi);   // odd-dim partials
                u64 t;
                // t = a*xsq + b + g*(pe+po)  ==  -0.5*log2e*dist2/sigma^2
                asm("fma.rn.f32x2 %0, %1, %2, %3;" : "=l"(t)
                    : "l"(ab.x), "l"(xsqd[r]), "l"(ab.y));
                FMA2(t, g, pe);
                FMA2(t, g, po);
                u32 t0, t1; unpack2(t, t0, t1);
                float e0, e1;
                asm("ex2.approx.ftz.f32 %0, %1;" : "=f"(e0) : "f"(__uint_as_float(t0)));
                asm("ex2.approx.ftz.f32 %0, %1;" : "=f"(e1) : "f"(__uint_as_float(t1)));
                u64 rp = pack2(__float_as_uint(e0), __float_as_uint(e1)), h;
                // h = (2^(t/2))^2 : subnormal-correct via non-ftz packed mul
                asm("mul.rn.f32x2 %0, %1, %2;" : "=l"(h) : "l"(rp), "l"(rp));
                FMA2(op[0][r], h, w0);
                FMA2(op[1][r], h, w1);
                FMA2(op[2][r], h, w2);
            }
        }
    }

    #pragma unroll
    for (int r = 0; r < R; ++r) {
        float* Or = O + (size_t)rows[r] * 3;
        u32 lo, hi;
        unpack2(op[0][r], lo, hi);
        Or[0] = __uint_as_float(lo) + __uint_as_float(hi) + bo0;
        unpack2(op[1][r], lo, hi);
        Or[1] = __uint_as_float(lo) + __uint_as_float(hi) + bo1;
        unpack2(op[2][r], lo, hi);
        Or[2] = __uint_as_float(lo) + __uint_as_float(hi) + bo2;
    }
}

__global__ void __launch_bounds__(NTH, 1)
rbfn_kernel(const float* __restrict__ X,    // [N, D]
            const float* __restrict__ Cn,   // [C, D]
            const float* __restrict__ Sg,   // [1, C]
            const float* __restrict__ Wp,   // [DO, C]
            const float* __restrict__ Bp,   // [DO]
            float* __restrict__ O)          // [N, 3]
{
    extern __shared__ unsigned char smem_raw[];
    const int tid = threadIdx.x;

    // stage centers row-major (straight float4 copy)
    {
        float4*       dst = (float4*)smem_raw;
        const float4* src = (const float4*)Cn;
        #pragma unroll
        for (int i = tid; i < NC * DIMS / 4; i += NTH) dst[i] = src[i];
    }
    // folded coefficient tables (one thread per center-pair)
    if (tid < NC2) {
        const int c2 = tid;
        float4* scoef = (float4*)(smem_raw + SMEM_COEF);
        float2* sg    = (float2*)(smem_raw + SMEM_G);
        float2* sw    = (float2*)(smem_raw + SMEM_W);
        float cs0 = 0.f, cs1 = 0.f;
        const float* ca = Cn + (2 * c2) * DIMS;
        const float* cb = Cn + (2 * c2 + 1) * DIMS;
        #pragma unroll 8
        for (int d = 0; d < DIMS; ++d) {
            cs0 = fmaf(ca[d], ca[d], cs0);
            cs1 = fmaf(cb[d], cb[d], cs1);
        }
        const float L = 1.4426950408889634f;   // log2(e)
        float s0 = Sg[2 * c2];     s0 = 1.0f / (s0 * s0);
        float s1 = Sg[2 * c2 + 1]; s1 = 1.0f / (s1 * s1);
        float a0 = -0.5f * L * s0, a1 = -0.5f * L * s1;
        scoef[c2] = make_float4(a0, a1, a0 * cs0, a1 * cs1);
        sg[c2]    = make_float2(L * s0, L * s1);
        sw[c2 * 3 + 0] = make_float2(Wp[0 * NC + 2 * c2], Wp[0 * NC + 2 * c2 + 1]);
        sw[c2 * 3 + 1] = make_float2(Wp[1 * NC + 2 * c2], Wp[1 * NC + 2 * c2 + 1]);
        sw[c2 * 3 + 2] = make_float2(Wp[2 * NC + 2 * c2], Wp[2 * NC + 2 * c2 + 1]);
    }
    __syncthreads();

    const int wid = tid >> 5, lane = tid & 31;
    const float bo0 = Bp[0], bo1 = Bp[1], bo2 = Bp[2];

    const int rb0 = (int)blockIdx.x + NBLK * wid;          // always < RBSPLIT
    const int r0  = (rb0 << 5) + lane;
    if (rb0 < PAIRMAX) {
        const int r1 = ((rb0 + RBSPLIT) << 5) + lane;
        process_rows<2>(X, O, r0, r1, smem_raw, bo0, bo1, bo2);
    } else {
        process_rows<1>(X, O, r0, r0, smem_raw, bo0, bo1, bo2);
    }
}

extern "C" void kernel_launch(void* const* d_in, const int* in_sizes, int n_in,
                              void* d_out, int out_size)
{
    const float* X = nullptr; const float* Cn = nullptr; const float* Sg = nullptr;
    const float* Wp = nullptr; const float* Bp = nullptr;
    for (int i = 0; i < n_in; ++i) {
        switch (in_sizes[i]) {
            case NROWS * DIMS: X  = (const float*)d_in[i]; break;
            case NC * DIMS:    Cn = (const float*)d_in[i]; break;
            case NC:           Sg = (const float*)d_in[i]; break;
            case 3 * NC:       Wp = (const float*)d_in[i]; break;
            case 3:            Bp = (const float*)d_in[i]; break;
            default: break;
        }
    }
    if (!X || !Cn || !Sg || !Wp || !Bp) {
        X  = (const float*)d_in[0]; Cn = (const float*)d_in[1];
        Sg = (const float*)d_in[2]; Wp = (const float*)d_in[3];
        Bp = (const float*)d_in[4];
    }

    cudaFuncSetAttribute(rbfn_kernel,
                         cudaFuncAttributeMaxDynamicSharedMemorySize, SMEM_BYTES);
    rbfn_kernel<<<NBLK, NTH, SMEM_BYTES>>>(X, Cn, Sg, Wp, Bp, (float*)d_out);
}

// round 3
// speedup vs baseline: 1.3931x; 1.0307x over previous
#include <cuda_runtime.h>
#include <cstdint>

#define NROWS   131072
#define DIMS    32
#define NC      512
#define NC2     256
#define NBLK    148
#define NTH     256
#define NWARPS  8
#define ROWBLKS 4096

typedef unsigned long long u64;
typedef unsigned int       u32;

// smem layout (bytes):
//   [0      , 65536) : centers row-major float[512][32]
//   [65536  , 69632) : coef float4 scoef[c2] = {a0, a1, b0, b1}
//   [69632  , 71680) : float2 sg[c2] = {g0, g1}
//   [71680  , 77824) : float2 sw[c2*3+k]
#define SMEM_COEF 65536
#define SMEM_G    (65536 + 4096)
#define SMEM_W    (65536 + 4096 + 2048)
#define SMEM_BYTES (65536 + 4096 + 2048 + 6144)

#define FMA2(acc, a, b) \
    asm("fma.rn.f32x2 %0, %1, %2, %0;" : "+l"(acc) : "l"(a), "l"(b))

__device__ __forceinline__ u64 dup2(float v) {
    u64 r; u32 u = __float_as_uint(v);
    asm("mov.b64 %0, {%1, %1};" : "=l"(r) : "r"(u));
    return r;
}
__device__ __forceinline__ u64 pack2(u32 a, u32 b) {
    u64 r; asm("mov.b64 %0, {%1, %2};" : "=l"(r) : "r"(a), "r"(b));
    return r;
}
__device__ __forceinline__ void unpack2(u64 v, u32& a, u32& b) {
    asm("mov.b64 {%0, %1}, %2;" : "=r"(a), "=r"(b) : "l"(v));
}

// Process R rows against all 512 centers. rows[] are absolute row indices.
template<int R>
__device__ __forceinline__ void process_rows(
    const float* __restrict__ X, float* __restrict__ O,
    const int* rows, const unsigned char* smem_raw,
    float bo0, float bo1, float bo2)
{
    const ulonglong2* sc    = (const ulonglong2*)(smem_raw);             // 8 per center
    const ulonglong2* scoef = (const ulonglong2*)(smem_raw + SMEM_COEF); // {a0,a1},{b0,b1}
    const u64*        sg    = (const u64*)(smem_raw + SMEM_G);
    const u64*        sw    = (const u64*)(smem_raw + SMEM_W);

    // x rows as packed dim-pairs + dup'd ||x||^2
    u64 xp[R][16];
    u64 xsqd[R];
    #pragma unroll
    for (int r = 0; r < R; ++r) {
        const ulonglong2* xr = (const ulonglong2*)(X + (size_t)rows[r] * DIMS);
        u64 sq = 0ull;
        #pragma unroll
        for (int q = 0; q < 8; ++q) {
            ulonglong2 v = xr[q];
            xp[r][2 * q]     = v.x;
            xp[r][2 * q + 1] = v.y;
            FMA2(sq, v.x, v.x);
            FMA2(sq, v.y, v.y);
        }
        u32 lo, hi; unpack2(sq, lo, hi);
        xsqd[r] = dup2(__uint_as_float(lo) + __uint_as_float(hi));
    }

    u64 op[3][R];
    #pragma unroll
    for (int k = 0; k < 3; ++k)
        #pragma unroll
        for (int r = 0; r < R; ++r) op[k][r] = 0ull;

    for (int c4 = 0; c4 < NC; c4 += 4) {
        u64 acc[4][R];
        #pragma unroll
        for (int cp = 0; cp < 4; ++cp)
            #pragma unroll
            for (int r = 0; r < R; ++r) acc[cp][r] = 0ull;

        const ulonglong2* p = sc + (size_t)c4 * 8;
        #pragma unroll
        for (int cp = 0; cp < 4; ++cp) {
            #pragma unroll
            for (int d8 = 0; d8 < 8; ++d8) {
                ulonglong2 u = p[cp * 8 + d8];         // 4 dims of center c4+cp
                #pragma unroll
                for (int r = 0; r < R; ++r) {
                    FMA2(acc[cp][r], xp[r][2 * d8],     u.x);
                    FMA2(acc[cp][r], xp[r][2 * d8 + 1], u.y);
                }
            }
        }

        // epilogue: center-pairs (c4,c4+1) and (c4+2,c4+3), packed over centers
        #pragma unroll
        for (int pp = 0; pp < 2; ++pp) {
            const int c2 = (c4 >> 1) + pp;
            ulonglong2 ab = scoef[c2];
            u64 g  = sg[c2];
            u64 w0 = sw[c2 * 3 + 0], w1 = sw[c2 * 3 + 1], w2 = sw[c2 * 3 + 2];
            #pragma unroll
            for (int r = 0; r < R; ++r) {
                u32 aLo, aHi, bLo, bHi;
                unpack2(acc[2 * pp][r],     aLo, aHi);
                unpack2(acc[2 * pp + 1][r], bLo, bHi);
                u64 pe = pack2(aLo, bLo);   // even-dim partials of both centers
                u64 po = pack2(aHi, bHi);   // odd-dim partials
                u64 t;
                // t = a*xsq + b + g*(pe+po)  ==  -0.5*log2e*dist2/sigma^2
                asm("fma.rn.f32x2 %0, %1, %2, %3;" : "=l"(t)
                    : "l"(ab.x), "l"(xsqd[r]), "l"(ab.y));
                FMA2(t, g, pe);
                FMA2(t, g, po);
                u32 t0, t1; unpack2(t, t0, t1);
                float e0, e1;
                asm("ex2.approx.ftz.f32 %0, %1;" : "=f"(e0) : "f"(__uint_as_float(t0)));
                asm("ex2.approx.ftz.f32 %0, %1;" : "=f"(e1) : "f"(__uint_as_float(t1)));
                u64 rp = pack2(__float_as_uint(e0), __float_as_uint(e1)), h;
                // h = (2^(t/2))^2 : subnormal-correct via non-ftz packed mul
                asm("mul.rn.f32x2 %0, %1, %2;" : "=l"(h) : "l"(rp), "l"(rp));
                FMA2(op[0][r], h, w0);
                FMA2(op[1][r], h, w1);
                FMA2(op[2][r], h, w2);
            }
        }
    }

    #pragma unroll
    for (int r = 0; r < R; ++r) {
        float* Or = O + (size_t)rows[r] * 3;
        u32 lo, hi;
        unpack2(op[0][r], lo, hi);
        Or[0] = __uint_as_float(lo) + __uint_as_float(hi) + bo0;
        unpack2(op[1][r], lo, hi);
        Or[1] = __uint_as_float(lo) + __uint_as_float(hi) + bo1;
        unpack2(op[2][r], lo, hi);
        Or[2] = __uint_as_float(lo) + __uint_as_float(hi) + bo2;
    }
}

__global__ void __launch_bounds__(NTH, 1)
rbfn_kernel(const float* __restrict__ X,    // [N, D]
            const float* __restrict__ Cn,   // [C, D]
            const float* __restrict__ Sg,   // [1, C]
            const float* __restrict__ Wp,   // [DO, C]
            const float* __restrict__ Bp,   // [DO]
            float* __restrict__ O)          // [N, 3]
{
    extern __shared__ unsigned char smem_raw[];
    const int tid = threadIdx.x;

    // stage centers row-major (straight float4 copy)
    {
        float4*       dst = (float4*)smem_raw;
        const float4* src = (const float4*)Cn;
        #pragma unroll
        for (int i = tid; i < NC * DIMS / 4; i += NTH) dst[i] = src[i];
    }
    // folded coefficient tables (one thread per center-pair)
    for (int c2 = tid; c2 < NC2; c2 += NTH) {
        float4* scoef = (float4*)(smem_raw + SMEM_COEF);
        float2* sg    = (float2*)(smem_raw + SMEM_G);
        float2* sw    = (float2*)(smem_raw + SMEM_W);
        float cs0 = 0.f, cs1 = 0.f;
        const float* ca = Cn + (2 * c2) * DIMS;
        const float* cb = Cn + (2 * c2 + 1) * DIMS;
        #pragma unroll 8
        for (int d = 0; d < DIMS; ++d) {
            cs0 = fmaf(ca[d], ca[d], cs0);
            cs1 = fmaf(cb[d], cb[d], cs1);
        }
        const float L = 1.4426950408889634f;   // log2(e)
        float s0 = Sg[2 * c2];     s0 = 1.0f / (s0 * s0);
        float s1 = Sg[2 * c2 + 1]; s1 = 1.0f / (s1 * s1);
        float a0 = -0.5f * L * s0, a1 = -0.5f * L * s1;
        scoef[c2] = make_float4(a0, a1, a0 * cs0, a1 * cs1);
        sg[c2]    = make_float2(L * s0, L * s1);
        sw[c2 * 3 + 0] = make_float2(Wp[0 * NC + 2 * c2], Wp[0 * NC + 2 * c2 + 1]);
        sw[c2 * 3 + 1] = make_float2(Wp[1 * NC + 2 * c2], Wp[1 * NC + 2 * c2 + 1]);
        sw[c2 * 3 + 2] = make_float2(Wp[2 * NC + 2 * c2], Wp[2 * NC + 2 * c2 + 1]);
    }
    __syncthreads();

    const int wid = tid >> 5, lane = tid & 31;
    const float bo0 = Bp[0], bo1 = Bp[1], bo2 = Bp[2];

    // CTA b owns rowblocks [b*4096/148, (b+1)*4096/148)  (27 or 28 blocks)
    const int nb_start = (int)(((long long)blockIdx.x * ROWBLKS) / NBLK);
    const int nb_end   = (int)((((long long)blockIdx.x + 1) * ROWBLKS) / NBLK);
    const int n        = nb_end - nb_start;

    // warp w takes tasks w, w+8, w+16, w+24  (3 or 4 of them)
    const int cnt = (n - wid + NWARPS - 1) / NWARPS;   // 3 or 4
    int rows[4];
    #pragma unroll
    for (int i = 0; i < 4; ++i)
        rows[i] = ((nb_start + wid + NWARPS * i) << 5) + lane;

    if (cnt == 4) {
        process_rows<4>(X, O, rows, smem_raw, bo0, bo1, bo2);
    } else {
        process_rows<3>(X, O, rows, smem_raw, bo0, bo1, bo2);
    }
}

extern "C" void kernel_launch(void* const* d_in, const int* in_sizes, int n_in,
                              void* d_out, int out_size)
{
    const float* X = nullptr; const float* Cn = nullptr; const float* Sg = nullptr;
    const float* Wp = nullptr; const float* Bp = nullptr;
    for (int i = 0; i < n_in; ++i) {
        switch (in_sizes[i]) {
            case NROWS * DIMS: X  = (const float*)d_in[i]; break;
            case NC * DIMS:    Cn = (const float*)d_in[i]; break;
            case NC:           Sg = (const float*)d_in[i]; break;
            case 3 * NC:       Wp = (const float*)d_in[i]; break;
            case 3:            Bp = (const float*)d_in[i]; break;
            default: break;
        }
    }
    if (!X || !Cn || !Sg || !Wp || !Bp) {
        X  = (const float*)d_in[0]; Cn = (const float*)d_in[1];
        Sg = (const float*)d_in[2]; Wp = (const float*)d_in[3];
        Bp = (const float*)d_in[4];
    }

    cudaFuncSetAttribute(rbfn_kernel,
                         cudaFuncAttributeMaxDynamicSharedMemorySize, SMEM_BYTES);
    rbfn_kernel<<<NBLK, NTH, SMEM_BYTES>>>(X, Cn, Sg, Wp, Bp, (float*)d_out);
}